// round 13
// baseline (speedup 1.0000x reference)
#include <cuda_runtime.h>
#include <cuda_fp16.h>
#include <cstdint>
#include <cstddef>

// Problem dims: y[b,m,n] = sum_k x[b,m,k] w[k,n]; flatten b,m -> M
#define MDIM 8192
#define KDIM 4096
#define NDIM 4096
#define KB16 (KDIM / 16)  // 256 k-blocks of 16

// GEMM tiling: CTA 128x128x64, 8 warps (2m x 4n), warp tile 64x32, 4 stages,
// 2 CTAs/SM. Flat 8-unit pipeline per kt. A fp16 smem; B permuted int8 smem.
#define BM 128
#define BN 128
#define BK 64
#define STAGES 4
#define KT (KDIM / BK)  // 64
#define THREADS 256

#define LDA 72                         // 64 + 8 pad (fp16 elems per A smem row)
#define A_TILE_B (BM * LDA * 2)        // 18432
#define B_TILE_B (4 * BN * 16)         // 8192: rows = kbl*128 + n, 16B each
#define STAGE_B (A_TILE_B + B_TILE_B)  // 26624
#define SMEM_B (STAGES * STAGE_B)      // 106496 -> 2 CTAs/SM

// scratch (allocation-free rule: __device__ globals)
__device__ __half g_xh[(size_t)MDIM * KDIM];  // 67 MB fp16 x
__device__ uint4 g_w8[(size_t)NDIM * KB16];   // 16.8 MB permuted int8 w+1

static __device__ __forceinline__ uint32_t smem_u32(const void* p) {
    uint32_t a;
    asm("{ .reg .u64 t; cvta.to.shared.u64 t, %1; cvt.u32.u64 %0, t; }"
        : "=r"(a) : "l"(p));
    return a;
}

#define CP_ASYNC16(dst, src) \
    asm volatile("cp.async.cg.shared.global [%0], [%1], 16;" :: "r"(dst), "l"(src))
#define CP_COMMIT() asm volatile("cp.async.commit_group;" ::: "memory")
#define CP_WAIT(n)  asm volatile("cp.async.wait_group %0;" :: "n"(n) : "memory")

#define LDMATRIX_X4(r0, r1, r2, r3, addr)                                  \
    asm volatile("ldmatrix.sync.aligned.m8n8.x4.shared.b16 "               \
                 "{%0,%1,%2,%3}, [%4];"                                    \
                 : "=r"(r0), "=r"(r1), "=r"(r2), "=r"(r3) : "r"(addr))

#define MMA16816(d, a, b0, b1)                                             \
    asm volatile("mma.sync.aligned.m16n8k16.row.col.f32.f16.f16.f32 "      \
                 "{%0,%1,%2,%3}, {%4,%5,%6,%7}, {%8,%9}, {%0,%1,%2,%3};"   \
                 : "+f"((d)[0]), "+f"((d)[1]), "+f"((d)[2]), "+f"((d)[3])  \
                 : "r"((a)[0]), "r"((a)[1]), "r"((a)[2]), "r"((a)[3]),     \
                   "r"(b0), "r"(b1))

// ---------------------------------------------------------------------------
// prep: x -> fp16; w -> permuted int8(+1), layout g_w8[n*KB16 + kb] (16B).
// Byte 4j+{0,1,2,3} of block (n,kb) = w[16kb + {2j, 2j+1, 2j+8, 2j+9}][n] + 1,
// so ldmatrix.x4.b16 delivers mma-B-fragment bytes directly (verified R7).
// ---------------------------------------------------------------------------
#define XCHUNKS ((size_t)MDIM * KDIM / 4)   // 8388608 float4s (x part)
#define WTHREADS ((size_t)NDIM * KB16)      // 1048576 (w part)

__global__ void cvt_kernel(const float4* __restrict__ x4,
                           const float* __restrict__ w) {
    size_t idx = (size_t)blockIdx.x * blockDim.x + threadIdx.x;
    if (idx < XCHUNKS) {
        float4 v = x4[idx];
        __half2 h0 = __floats2half2_rn(v.x, v.y);
        __half2 h1 = __floats2half2_rn(v.z, v.w);
        uint2 o;
        o.x = *reinterpret_cast<uint32_t*>(&h0);
        o.y = *reinterpret_cast<uint32_t*>(&h1);
        reinterpret_cast<uint2*>(g_xh)[idx] = o;
    } else {
        size_t wi = idx - XCHUNKS;
        int n = (int)(wi & (NDIM - 1));
        int kb = (int)(wi >> 12);
        const float* col = w + (size_t)(kb * 16) * NDIM + n;
        uint32_t q[4];
#pragma unroll
        for (int j = 0; j < 4; ++j) {
            uint32_t b0 = (uint32_t)(int)(col[(size_t)(2 * j) * NDIM] + 1.0f);
            uint32_t b1 = (uint32_t)(int)(col[(size_t)(2 * j + 1) * NDIM] + 1.0f);
            uint32_t b2 = (uint32_t)(int)(col[(size_t)(2 * j + 8) * NDIM] + 1.0f);
            uint32_t b3 = (uint32_t)(int)(col[(size_t)(2 * j + 9) * NDIM] + 1.0f);
            q[j] = b0 | (b1 << 8) | (b2 << 16) | (b3 << 24);
        }
        g_w8[(size_t)n * KB16 + kb] = make_uint4(q[0], q[1], q[2], q[3]);
    }
}

// ---------------------------------------------------------------------------
// GEMM
// ---------------------------------------------------------------------------
__global__ void __launch_bounds__(THREADS, 2) gemm_kernel(float* __restrict__ out) {
    extern __shared__ char smem_raw[];
    const uint32_t smem = smem_u32(smem_raw);

    const int tid = threadIdx.x;
    const int lane = tid & 31;
    const int wid = tid >> 5;
    const int warp_m = wid & 1;   // 0..1
    const int warp_n = wid >> 1;  // 0..3

    const int m0 = blockIdx.y * BM;
    const int n0 = blockIdx.x * BN;

    // ---- cp.async bases ----
    // A tile: 128 rows x 64 halfs -> 1024 chunks of 16B, 4/thread (rows +32*i)
    const int rA = tid >> 3, chA = tid & 7;
    const uint32_t sA0 = smem + (uint32_t)(rA * LDA + chA * 8) * 2;
    const __half* gA0 = g_xh + (size_t)(m0 + rA) * KDIM + chA * 8;
    // B tile: 512 rows... -> 512 chunks of 16B, 2/thread (R7 layout)
    const int bn = tid & 127;
    const int bkbl = tid >> 7;  // 0 or 1; second chunk is kbl+2
    const uint8_t* gB0 =
        reinterpret_cast<const uint8_t*>(g_w8) +
        ((size_t)(n0 + bn) * KB16 + bkbl) * 16;
    const uint32_t sB0 = smem + A_TILE_B + (uint32_t)tid * 16;

#define ISSUE_KT(slot, kt_)                                                  \
    do {                                                                     \
        const uint32_t sb = (uint32_t)(slot) * STAGE_B;                      \
        const size_t kb = (size_t)(kt_) * BK;                                \
        _Pragma("unroll")                                                    \
        for (int i = 0; i < 4; ++i)                                          \
            CP_ASYNC16(sA0 + sb + (uint32_t)(i * 32 * LDA * 2),              \
                       gA0 + (size_t)i * 32 * KDIM + kb);                    \
        CP_ASYNC16(sB0 + sb, gB0 + (size_t)(kt_) * 64);                      \
        CP_ASYNC16(sB0 + sb + 4096, gB0 + (size_t)(kt_) * 64 + 32);          \
    } while (0)

    // ---- fragment base addresses ----
    const uint32_t a_frag =
        smem + (uint32_t)((warp_m * 64 + (lane & 15)) * LDA + (lane >> 4) * 8) * 2;
    // B: lane l supplies row (kk*128 + warp_n*32 + l) of 16B
    const uint32_t b_frag = smem + A_TILE_B + (uint32_t)(warp_n * 32 + lane) * 16;

    // fragment buffers
    uint32_t a_f[2][2][4];   // [unit parity][j]
    uint32_t braw[2][4];     // [kk parity] raw int8 B fragments
    uint32_t b0[4], b1[4];   // expanded fp16 B for current kk

#define LOAD_A_HALF(ab, base, h, kk)                                         \
    do {                                                                     \
        _Pragma("unroll")                                                    \
        for (int j = 0; j < 2; ++j)                                          \
            LDMATRIX_X4(a_f[ab][j][0], a_f[ab][j][1], a_f[ab][j][2],         \
                        a_f[ab][j][3],                                       \
                        (base) + (uint32_t)((((h) * 2 + j) * 16) * LDA +     \
                                            (kk) * 16) * 2);                 \
    } while (0)

#define LOAD_BRAW(bb, base, kk)                                              \
    LDMATRIX_X4(braw[bb][0], braw[bb][1], braw[bb][2], braw[bb][3],          \
                (base) + (uint32_t)((kk) * 128) * 16)

// batched int8(w+1) -> fp16 expansion: 8 prmt then 8 sub (exact arithmetic)
#define EXPAND_B(bb)                                                         \
    do {                                                                     \
        const uint32_t MAG = 0x64646464u, BIAS = 0x64016401u;                \
        uint32_t lo_[4], hi_[4];                                             \
        _Pragma("unroll")                                                    \
        for (int nj = 0; nj < 4; ++nj) {                                     \
            asm("prmt.b32 %0, %1, %2, 0x4140;"                               \
                : "=r"(lo_[nj]) : "r"(braw[bb][nj]), "r"(MAG));              \
            asm("prmt.b32 %0, %1, %2, 0x4342;"                               \
                : "=r"(hi_[nj]) : "r"(braw[bb][nj]), "r"(MAG));              \
        }                                                                    \
        _Pragma("unroll")                                                    \
        for (int nj = 0; nj < 4; ++nj) {                                     \
            asm("sub.f16x2 %0, %1, %2;" : "=r"(b0[nj]) : "r"(lo_[nj]), "r"(BIAS)); \
            asm("sub.f16x2 %0, %1, %2;" : "=r"(b1[nj]) : "r"(hi_[nj]), "r"(BIAS)); \
        }                                                                    \
    } while (0)

    float acc[4][4][4];
#pragma unroll
    for (int mi = 0; mi < 4; ++mi)
#pragma unroll
        for (int ni = 0; ni < 4; ++ni)
#pragma unroll
            for (int q = 0; q < 4; ++q) acc[mi][ni][q] = 0.f;

    // ---- prologue: fill all 4 stages; wait so slots 0,1 complete ----
    ISSUE_KT(0, 0); CP_COMMIT();
    ISSUE_KT(1, 1); CP_COMMIT();
    ISSUE_KT(2, 2); CP_COMMIT();
    ISSUE_KT(3, 3); CP_COMMIT();
    CP_WAIT(2);
    __syncthreads();

    // preload unit 0 of kt 0
    LOAD_A_HALF(0, a_frag, 0, 0);
    LOAD_BRAW(0, b_frag, 0);

    // ---- mainloop ----
    for (int kt = 0; kt < KT; ++kt) {
        const uint32_t sb  = (uint32_t)(kt & 3) * STAGE_B;
        const uint32_t sbn = (uint32_t)((kt + 1) & 3) * STAGE_B;
        const uint32_t aB  = a_frag + sb,  bB  = b_frag + sb;
        const uint32_t aBn = a_frag + sbn, bBn = b_frag + sbn;

#pragma unroll
        for (int u = 0; u < 8; ++u) {
            const int kk = u >> 1, h = u & 1;
            // expand this kk's B at its first unit (raw loaded >=1 unit ago)
            if (h == 0) EXPAND_B(kk & 1);
            // load fragments for unit u+1 (cross-kt at u==7)
            if (u < 7) {
                const int un = u + 1, kkn = un >> 1, hn = un & 1;
                LOAD_A_HALF(un & 1, aB, hn, kkn);
                if (hn == 0) LOAD_BRAW(kkn & 1, bB, kkn);
            } else if (kt + 1 < KT) {
                LOAD_A_HALF(0, aBn, 0, 0);
                LOAD_BRAW(0, bBn, 0);
            }
            // MMAs for unit u
#pragma unroll
            for (int j = 0; j < 2; ++j) {
                const int mi = h * 2 + j;
#pragma unroll
                for (int nj = 0; nj < 4; ++nj)
                    MMA16816(acc[mi][nj], a_f[u & 1][j], b0[nj], b1[nj]);
            }
        }

        // ---- stage rotation ----
        __syncthreads();                       // all warps done with slot kt
        if (kt + 4 < KT) ISSUE_KT(kt & 3, kt + 4);
        CP_COMMIT();
        CP_WAIT(2);                            // slot kt+2 complete
        __syncthreads();                       // ...and visible
    }

    // ---- epilogue: direct fp32 stores ----
    const int mg = m0 + warp_m * 64 + (lane >> 2);
    const int ng = n0 + warp_n * 32 + (lane & 3) * 2;
#pragma unroll
    for (int mi = 0; mi < 4; ++mi) {
#pragma unroll
        for (int ni = 0; ni < 4; ++ni) {
            float* p0 = out + (size_t)(mg + mi * 16) * NDIM + ng + ni * 8;
            float* p1 = p0 + 8 * NDIM;
            *reinterpret_cast<float2*>(p0) = make_float2(acc[mi][ni][0], acc[mi][ni][1]);
            *reinterpret_cast<float2*>(p1) = make_float2(acc[mi][ni][2], acc[mi][ni][3]);
        }
    }
}

// ---------------------------------------------------------------------------
extern "C" void kernel_launch(void* const* d_in, const int* in_sizes, int n_in,
                              void* d_out, int out_size) {
    const float* x = (const float*)d_in[0];  // (4, 2048, 4096) fp32
    const float* w = (const float*)d_in[1];  // (4096, 4096) fp32 ternary
    float* out = (float*)d_out;              // (4, 2048, 4096) fp32

    size_t total = XCHUNKS + WTHREADS;  // 9437184
    cvt_kernel<<<(int)(total / 256), 256>>>(
        reinterpret_cast<const float4*>(x), w);

    cudaFuncSetAttribute(gemm_kernel, cudaFuncAttributeMaxDynamicSharedMemorySize,
                         SMEM_B);
    dim3 grid(NDIM / BN, MDIM / BM);  // (32, 64)
    gemm_kernel<<<grid, THREADS, SMEM_B>>>(out);
}

// round 14
// speedup vs baseline: 1.1964x; 1.1964x over previous
#include <cuda_runtime.h>
#include <cuda_fp16.h>
#include <cstdint>
#include <cstddef>

// Problem dims: y[b,m,n] = sum_k x[b,m,k] w[k,n]; flatten b,m -> M
#define MDIM 8192
#define KDIM 4096
#define NDIM 4096

// GEMM tiling: CTA 128x128x64, 4 warps (2m x 2n), warp tile 64x64, 3 stages,
// 2 CTAs/SM, flat 8-unit pipeline per kt. Crossbar 1500 cyc < tensor 2048.
#define BM 128
#define BN 128
#define BK 64
#define STAGES 3
#define KT (KDIM / BK)  // 64
#define THREADS 128

#define LDA 72   // 64 + 8 pad (fp16 elems per A smem row)
#define LDB 136  // 128 + 8 pad
#define A_TILE_B (BM * LDA * 2)        // 18432
#define B_TILE_B (BK * LDB * 2)        // 17408
#define STAGE_B (A_TILE_B + B_TILE_B)  // 35840
#define SMEM_B (STAGES * STAGE_B)      // 107520 -> 2 CTAs/SM

// fp16 scratch (allocation-free rule: __device__ globals)
__device__ __half g_xh[(size_t)MDIM * KDIM];  // 67 MB
__device__ __half g_wh[(size_t)KDIM * NDIM];  // 33.5 MB

static __device__ __forceinline__ uint32_t smem_u32(const void* p) {
    uint32_t a;
    asm("{ .reg .u64 t; cvta.to.shared.u64 t, %1; cvt.u32.u64 %0, t; }"
        : "=r"(a) : "l"(p));
    return a;
}

#define CP_ASYNC16(dst, src) \
    asm volatile("cp.async.cg.shared.global [%0], [%1], 16;" :: "r"(dst), "l"(src))
#define CP_COMMIT() asm volatile("cp.async.commit_group;" ::: "memory")
#define CP_WAIT(n)  asm volatile("cp.async.wait_group %0;" :: "n"(n) : "memory")

#define LDMATRIX_X4(r, addr)                                               \
    asm volatile("ldmatrix.sync.aligned.m8n8.x4.shared.b16 "               \
                 "{%0,%1,%2,%3}, [%4];"                                    \
                 : "=r"((r)[0]), "=r"((r)[1]), "=r"((r)[2]), "=r"((r)[3])  \
                 : "r"(addr))

#define LDMATRIX_X4_T(r, addr)                                             \
    asm volatile("ldmatrix.sync.aligned.m8n8.x4.trans.shared.b16 "         \
                 "{%0,%1,%2,%3}, [%4];"                                    \
                 : "=r"((r)[0]), "=r"((r)[1]), "=r"((r)[2]), "=r"((r)[3])  \
                 : "r"(addr))

#define MMA16816(d, a, b0, b1)                                             \
    asm volatile("mma.sync.aligned.m16n8k16.row.col.f32.f16.f16.f32 "      \
                 "{%0,%1,%2,%3}, {%4,%5,%6,%7}, {%8,%9}, {%0,%1,%2,%3};"   \
                 : "+f"((d)[0]), "+f"((d)[1]), "+f"((d)[2]), "+f"((d)[3])  \
                 : "r"((a)[0]), "r"((a)[1]), "r"((a)[2]), "r"((a)[3]),     \
                   "r"(b0), "r"(b1))

// ---------------------------------------------------------------------------
// prep: fused fp32 -> fp16 for both x and w (one launch)
// ---------------------------------------------------------------------------
#define XCHUNKS ((size_t)MDIM * KDIM / 4)  // 8388608 float4s
#define WCHUNKS ((size_t)KDIM * NDIM / 4)  // 4194304 float4s

__global__ void cvt_both_kernel(const float4* __restrict__ x4,
                                const float4* __restrict__ w4) {
    size_t i = (size_t)blockIdx.x * blockDim.x + threadIdx.x;
    const float4* src;
    uint2* dst;
    if (i < XCHUNKS) {
        src = x4 + i;
        dst = reinterpret_cast<uint2*>(g_xh) + i;
    } else {
        src = w4 + (i - XCHUNKS);
        dst = reinterpret_cast<uint2*>(g_wh) + (i - XCHUNKS);
    }
    float4 v = *src;
    __half2 h0 = __floats2half2_rn(v.x, v.y);
    __half2 h1 = __floats2half2_rn(v.z, v.w);
    uint2 o;
    o.x = *reinterpret_cast<uint32_t*>(&h0);
    o.y = *reinterpret_cast<uint32_t*>(&h1);
    *dst = o;
}

// ---------------------------------------------------------------------------
// GEMM
// ---------------------------------------------------------------------------
__global__ void __launch_bounds__(THREADS, 2) gemm_kernel(float* __restrict__ out) {
    extern __shared__ char smem_raw[];
    const uint32_t smem = smem_u32(smem_raw);

    const int tid = threadIdx.x;
    const int lane = tid & 31;
    const int wid = tid >> 5;
    const int warp_m = wid & 1;   // 0..1
    const int warp_n = wid >> 1;  // 0..1

    const int m0 = blockIdx.y * BM;
    const int n0 = blockIdx.x * BN;

    // ---- cp.async bases: A 1024 chunks (8/thread), B 1024 chunks (8/thread)
    const int rA = tid >> 3, chA = tid & 7;    // A rows 0..15 (+16*i), 8 ch/row
    const uint32_t sA0 = smem + (uint32_t)(rA * LDA + chA * 8) * 2;
    const __half* gA0 = g_xh + (size_t)(m0 + rA) * KDIM + chA * 8;
    const int rB = tid >> 4, chB = tid & 15;   // B rows 0..7 (+8*i), 16 ch/row
    const uint32_t sB0 = smem + A_TILE_B + (uint32_t)(rB * LDB + chB * 8) * 2;
    const __half* gB0 = g_wh + (size_t)rB * NDIM + n0 + chB * 8;

#define ISSUE_KT(slot, kt_)                                                  \
    do {                                                                     \
        const uint32_t sb = (uint32_t)(slot) * STAGE_B;                      \
        const size_t kb = (size_t)(kt_) * BK;                                \
        _Pragma("unroll")                                                    \
        for (int i = 0; i < 8; ++i)                                          \
            CP_ASYNC16(sA0 + sb + (uint32_t)(i * 16 * LDA * 2),              \
                       gA0 + (size_t)i * 16 * KDIM + kb);                    \
        _Pragma("unroll")                                                    \
        for (int i = 0; i < 8; ++i)                                          \
            CP_ASYNC16(sB0 + sb + (uint32_t)(i * 8 * LDB * 2),               \
                       gB0 + ((size_t)i * 8 + kb) * NDIM);                   \
    } while (0)

    // ---- fragment base addresses ----
    const uint32_t a_frag =
        smem + (uint32_t)((warp_m * 64 + (lane & 15)) * LDA + (lane >> 4) * 8) * 2;
    const uint32_t b_frag =
        smem + A_TILE_B +
        (uint32_t)((lane & 15) * LDB + warp_n * 64 + (lane >> 4) * 8) * 2;

    // fragment buffers: a_f[unit parity][j], b_f[kk parity][njblk(16n)]
    uint32_t a_f[2][2][4], b_f[2][4][4];

#define LOAD_A_HALF(ab, base, h, kk)                                         \
    do {                                                                     \
        _Pragma("unroll")                                                    \
        for (int j = 0; j < 2; ++j)                                          \
            LDMATRIX_X4(a_f[ab][j],                                          \
                        (base) + (uint32_t)((((h) * 2 + j) * 16) * LDA +     \
                                            (kk) * 16) * 2);                 \
    } while (0)

// load half (p = 0,1) of a kk's B fragments: njblk = 2p, 2p+1
#define LOAD_B_HALF(bb, base, kk, p)                                         \
    do {                                                                     \
        _Pragma("unroll")                                                    \
        for (int t = 0; t < 2; ++t)                                          \
            LDMATRIX_X4_T(b_f[bb][2 * (p) + t],                              \
                          (base) + (uint32_t)((kk) * 16 * LDB +              \
                                              (2 * (p) + t) * 16) * 2);      \
    } while (0)

    float acc[4][8][4];
#pragma unroll
    for (int mi = 0; mi < 4; ++mi)
#pragma unroll
        for (int ni = 0; ni < 8; ++ni)
#pragma unroll
            for (int q = 0; q < 4; ++q) acc[mi][ni][q] = 0.f;

    // ---- prologue: fill all 3 stages; slots 0,1 complete ----
    ISSUE_KT(0, 0); CP_COMMIT();
    ISSUE_KT(1, 1); CP_COMMIT();
    ISSUE_KT(2, 2); CP_COMMIT();
    CP_WAIT(1);
    __syncthreads();

    // preload unit 0 of kt 0: A(h0,kk0) parity 0 + full B(kk0) parity 0
    LOAD_A_HALF(0, a_frag, 0, 0);
    LOAD_B_HALF(0, b_frag, 0, 0);
    LOAD_B_HALF(0, b_frag, 0, 1);

    // ---- mainloop ----
    for (int kt = 0; kt < KT; ++kt) {
        const uint32_t sb  = (uint32_t)(kt % 3) * STAGE_B;
        const uint32_t sbn = (uint32_t)((kt + 1) % 3) * STAGE_B;
        const uint32_t aB  = a_frag + sb,  bB  = b_frag + sb;
        const uint32_t aBn = a_frag + sbn, bBn = b_frag + sbn;

#pragma unroll
        for (int u = 0; u < 8; ++u) {
            const int kk = u >> 1, h = u & 1;
            // ---- prefetch fragments ----
            if (u < 7) {
                const int un = u + 1;
                LOAD_A_HALF(un & 1, aB, un & 1, un >> 1);
            } else if (kt + 1 < KT) {
                LOAD_A_HALF(0, aBn, 0, 0);
            }
            // B(kk+1) spread over this kk's two units (cross-kt at kk==3)
            if (kk < 3) {
                LOAD_B_HALF((kk + 1) & 1, bB, kk + 1, h);
            } else if (kt + 1 < KT) {
                LOAD_B_HALF(0, bBn, 0, h);
            }
            // ---- 16 MMAs for unit u ----
#pragma unroll
            for (int j = 0; j < 2; ++j) {
                const int mi = h * 2 + j;
#pragma unroll
                for (int nb = 0; nb < 4; ++nb) {
                    MMA16816(acc[mi][2 * nb + 0], a_f[u & 1][j],
                             b_f[kk & 1][nb][0], b_f[kk & 1][nb][1]);
                    MMA16816(acc[mi][2 * nb + 1], a_f[u & 1][j],
                             b_f[kk & 1][nb][2], b_f[kk & 1][nb][3]);
                }
            }
        }

        // ---- stage rotation (R12 invariant: slots kt+1, kt+2 ready) ----
        __syncthreads();                       // all warps done with slot kt
        if (kt + 3 < KT) ISSUE_KT(kt % 3, kt + 3);
        CP_COMMIT();
        CP_WAIT(1);                            // slot kt+2 complete
        __syncthreads();                       // ...and visible
    }

    // ---- epilogue: direct fp32 stores ----
    const int mg = m0 + warp_m * 64 + (lane >> 2);
    const int ng = n0 + warp_n * 64 + (lane & 3) * 2;
#pragma unroll
    for (int mi = 0; mi < 4; ++mi) {
#pragma unroll
        for (int ni = 0; ni < 8; ++ni) {
            float* p0 = out + (size_t)(mg + mi * 16) * NDIM + ng + ni * 8;
            float* p1 = p0 + 8 * NDIM;
            *reinterpret_cast<float2*>(p0) = make_float2(acc[mi][ni][0], acc[mi][ni][1]);
            *reinterpret_cast<float2*>(p1) = make_float2(acc[mi][ni][2], acc[mi][ni][3]);
        }
    }
}

// ---------------------------------------------------------------------------
extern "C" void kernel_launch(void* const* d_in, const int* in_sizes, int n_in,
                              void* d_out, int out_size) {
    const float* x = (const float*)d_in[0];  // (4, 2048, 4096) fp32
    const float* w = (const float*)d_in[1];  // (4096, 4096) fp32 ternary
    float* out = (float*)d_out;              // (4, 2048, 4096) fp32

    size_t total_chunks = XCHUNKS + WCHUNKS;  // 12582912
    cvt_both_kernel<<<(int)(total_chunks / 256), 256>>>(
        reinterpret_cast<const float4*>(x), reinterpret_cast<const float4*>(w));

    cudaFuncSetAttribute(gemm_kernel, cudaFuncAttributeMaxDynamicSharedMemorySize,
                         SMEM_B);
    dim3 grid(NDIM / BN, MDIM / BM);  // (32, 64)
    gemm_kernel<<<grid, THREADS, SMEM_B>>>(out);
}